// round 1
// baseline (speedup 1.0000x reference)
#include <cuda_runtime.h>

// RNNModel: 2-layer tanh RNN (batch_first) + FC(H->1) on last timestep.
// B=2048, T=512, I=8, H=64.
// Strategy: fused single kernel, one warp per batch element.
//  - Weights transposed into SMEM once per block (Wt[k][j] = W[j][k]).
//  - h0/h1 state in registers: lane holds h[2*lane], h[2*lane+1].
//  - h[k] broadcast via __shfl_sync; weight rows read as conflict-free float2 LDS.
//  - x prefetched one step ahead (2 broadcast float4 loads per step).

#define BB 2048
#define TT 512
#define II 8
#define HH 64
#define WARPS_PER_BLOCK 8
#define NTHREADS 256
#define FULLMASK 0xffffffffu

extern __shared__ float smem_dyn[];

__global__ void __launch_bounds__(NTHREADS)
rnn_fused_kernel(const float* __restrict__ x,
                 const float* __restrict__ W_ih0,
                 const float* __restrict__ W_hh0,
                 const float* __restrict__ b_ih0,
                 const float* __restrict__ b_hh0,
                 const float* __restrict__ W_ih1,
                 const float* __restrict__ W_hh1,
                 const float* __restrict__ b_ih1,
                 const float* __restrict__ b_hh1,
                 const float* __restrict__ fc_w,
                 const float* __restrict__ fc_b,
                 float* __restrict__ out)
{
    // SMEM layout (floats):
    // [0,4096)      whh0t   (Wt[k*64+j] = W_hh0[j*64+k])
    // [4096,8192)   wih1t
    // [8192,12288)  whh1t
    // [12288,12800) wih0t   (Wt[i*64+j] = W_ih0[j*8+i])
    // [12800,12864) bias0   (b_ih0 + b_hh0)
    // [12864,12928) bias1
    // [12928,12992) fcw
    float* whh0t = smem_dyn;
    float* wih1t = smem_dyn + 4096;
    float* whh1t = smem_dyn + 8192;
    float* wih0t = smem_dyn + 12288;
    float* bias0 = smem_dyn + 12800;
    float* bias1 = smem_dyn + 12864;
    float* fcw   = smem_dyn + 12928;

    const int tid = threadIdx.x;

    // One-time transposed weight load.
    for (int i = tid; i < 4096; i += NTHREADS) {
        int j = i >> 6;      // row of original (output index)
        int k = i & 63;      // col of original (input index)
        whh0t[k * 64 + j] = W_hh0[i];
        wih1t[k * 64 + j] = W_ih1[i];
        whh1t[k * 64 + j] = W_hh1[i];
    }
    for (int i = tid; i < 512; i += NTHREADS) {
        int j = i >> 3;
        int k = i & 7;
        wih0t[k * 64 + j] = W_ih0[i];
    }
    if (tid < 64) {
        bias0[tid] = b_ih0[tid] + b_hh0[tid];
        bias1[tid] = b_ih1[tid] + b_hh1[tid];
        fcw[tid]   = fc_w[tid];
    }
    __syncthreads();

    const int warp = tid >> 5;
    const int lane = tid & 31;
    const int b = blockIdx.x * WARPS_PER_BLOCK + warp;

    const float4* __restrict__ xrow =
        reinterpret_cast<const float4*>(x + (size_t)b * TT * II);

    const float2* __restrict__ whh0t2 = reinterpret_cast<const float2*>(whh0t);
    const float2* __restrict__ wih1t2 = reinterpret_cast<const float2*>(wih1t);
    const float2* __restrict__ whh1t2 = reinterpret_cast<const float2*>(whh1t);
    const float2* __restrict__ wih0t2 = reinterpret_cast<const float2*>(wih0t);

    float2 h0 = make_float2(0.f, 0.f);
    float2 h1 = make_float2(0.f, 0.f);

    const float2 bv0 = reinterpret_cast<const float2*>(bias0)[lane];
    const float2 bv1 = reinterpret_cast<const float2*>(bias1)[lane];

    // Prefetch x for t=0 (all lanes read same address -> broadcast, 1 sector each).
    float4 xa = xrow[0];
    float4 xb = xrow[1];

    for (int t = 0; t < TT; t++) {
        // Prefetch next step's x (independent of recurrence).
        const int tn = (t < TT - 1) ? (t + 1) : t;
        float4 nxa = xrow[2 * tn];
        float4 nxb = xrow[2 * tn + 1];

        // ---- layer 0: pre = bias0 + x_t @ W_ih0^T ----
        float2 a0 = bv0;
        float2 a0b = make_float2(0.f, 0.f);
        {
            float2 w;
            w = wih0t2[0 * 32 + lane]; a0.x  += xa.x * w.x; a0.y  += xa.x * w.y;
            w = wih0t2[1 * 32 + lane]; a0b.x += xa.y * w.x; a0b.y += xa.y * w.y;
            w = wih0t2[2 * 32 + lane]; a0.x  += xa.z * w.x; a0.y  += xa.z * w.y;
            w = wih0t2[3 * 32 + lane]; a0b.x += xa.w * w.x; a0b.y += xa.w * w.y;
            w = wih0t2[4 * 32 + lane]; a0.x  += xb.x * w.x; a0.y  += xb.x * w.y;
            w = wih0t2[5 * 32 + lane]; a0b.x += xb.y * w.x; a0b.y += xb.y * w.y;
            w = wih0t2[6 * 32 + lane]; a0.x  += xb.z * w.x; a0.y  += xb.z * w.y;
            w = wih0t2[7 * 32 + lane]; a0b.x += xb.w * w.x; a0b.y += xb.w * w.y;
        }

        // ---- layer 0 recurrence: + h0 @ W_hh0^T ----
        #pragma unroll
        for (int m = 0; m < 32; m++) {
            float hx = __shfl_sync(FULLMASK, h0.x, m);
            float hy = __shfl_sync(FULLMASK, h0.y, m);
            float2 w0 = whh0t2[(2 * m)     * 32 + lane];
            float2 w1 = whh0t2[(2 * m + 1) * 32 + lane];
            a0.x  += hx * w0.x; a0.y  += hx * w0.y;
            a0b.x += hy * w1.x; a0b.y += hy * w1.y;
        }
        h0.x = tanhf(a0.x + a0b.x);
        h0.y = tanhf(a0.y + a0b.y);

        // ---- layer 1: pre = bias1 + h0_t @ W_ih1^T + h1 @ W_hh1^T ----
        float2 a1 = bv1;
        float2 a1b = make_float2(0.f, 0.f);
        #pragma unroll
        for (int m = 0; m < 32; m++) {
            float hx = __shfl_sync(FULLMASK, h0.x, m);
            float hy = __shfl_sync(FULLMASK, h0.y, m);
            float2 w0 = wih1t2[(2 * m)     * 32 + lane];
            float2 w1 = wih1t2[(2 * m + 1) * 32 + lane];
            a1.x  += hx * w0.x; a1.y  += hx * w0.y;
            a1b.x += hy * w1.x; a1b.y += hy * w1.y;
        }
        #pragma unroll
        for (int m = 0; m < 32; m++) {
            float hx = __shfl_sync(FULLMASK, h1.x, m);
            float hy = __shfl_sync(FULLMASK, h1.y, m);
            float2 w0 = whh1t2[(2 * m)     * 32 + lane];
            float2 w1 = whh1t2[(2 * m + 1) * 32 + lane];
            a1.x  += hx * w0.x; a1.y  += hx * w0.y;
            a1b.x += hy * w1.x; a1b.y += hy * w1.y;
        }
        h1.x = tanhf(a1.x + a1b.x);
        h1.y = tanhf(a1.y + a1b.y);

        xa = nxa;
        xb = nxb;
    }

    // ---- FC: out[b] = h1_last . fc_w + fc_b ----
    const float2 fw = reinterpret_cast<const float2*>(fcw)[lane];
    float s = h1.x * fw.x + h1.y * fw.y;
    #pragma unroll
    for (int off = 16; off > 0; off >>= 1)
        s += __shfl_xor_sync(FULLMASK, s, off);
    if (lane == 0)
        out[b] = s + fc_b[0];
}

extern "C" void kernel_launch(void* const* d_in, const int* in_sizes, int n_in,
                              void* d_out, int out_size)
{
    const float* x     = (const float*)d_in[0];
    const float* W_ih0 = (const float*)d_in[1];
    const float* W_hh0 = (const float*)d_in[2];
    const float* b_ih0 = (const float*)d_in[3];
    const float* b_hh0 = (const float*)d_in[4];
    const float* W_ih1 = (const float*)d_in[5];
    const float* W_hh1 = (const float*)d_in[6];
    const float* b_ih1 = (const float*)d_in[7];
    const float* b_hh1 = (const float*)d_in[8];
    const float* fc_w  = (const float*)d_in[9];
    const float* fc_b  = (const float*)d_in[10];
    float* out = (float*)d_out;

    const int smem_bytes = 12992 * sizeof(float);  // 51968 B
    cudaFuncSetAttribute(rnn_fused_kernel,
                         cudaFuncAttributeMaxDynamicSharedMemorySize, smem_bytes);

    dim3 grid(BB / WARPS_PER_BLOCK);   // 256 blocks
    dim3 block(NTHREADS);              // 8 warps, 1 batch element per warp
    rnn_fused_kernel<<<grid, block, smem_bytes>>>(
        x, W_ih0, W_hh0, b_ih0, b_hh0,
        W_ih1, W_hh1, b_ih1, b_hh1,
        fc_w, fc_b, out);
}

// round 3
// speedup vs baseline: 1.3678x; 1.3678x over previous
#include <cuda_runtime.h>

// RNNModel: 2-layer tanh RNN + FC, B=2048, T=512, I=8, H=64.
// Design: weights in REGISTERS (k-packed f32x2 pairs), h-state exchanged via
// broadcast-only SMEM, fma.rn.f32x2 for the dot products.
//  - 2 warps per batch element; lane = one output column j (j = half*32 + lane).
//  - Each lane owns row j of W_hh0, W_ih1, W_hh1 (32 packed pairs each) + W_ih0 (2 pairs).
//  - h vectors double-buffered in SMEM; one named barrier (per 64-thread group) per step.
// (R2 resubmit: R1 bench died with harness-side cudaErrorSystemNotReady before
//  the kernel ever ran — infra transient, no kernel signal.)

#define TT 512
#define HH 64
#define GROUPS 4            // batch elements per block (each = 2 warps)
#define NTHREADS 256        // 8 warps
#define BB 2048
#define FULLMASK 0xffffffffu

typedef unsigned long long ull;

__device__ __forceinline__ ull ffma2(ull h, ull w, ull c) {
    ull d;
    asm("fma.rn.f32x2 %0, %1, %2, %3;" : "=l"(d) : "l"(h), "l"(w), "l"(c));
    return d;
}
__device__ __forceinline__ ull fadd2(ull a, ull b) {
    ull d;
    asm("add.rn.f32x2 %0, %1, %2;" : "=l"(d) : "l"(a), "l"(b));
    return d;
}
__device__ __forceinline__ float2 unpk(ull v) {
    float2 r;
    asm("mov.b64 {%0, %1}, %2;" : "=f"(r.x), "=f"(r.y) : "l"(v));
    return r;
}

struct __align__(16) GroupSmem {
    float h0[2][HH];   // double-buffered layer-0 hidden state
    float h1[2][HH];   // double-buffered layer-1 hidden state
    float part[4];     // FC partials (+pad to 16B multiple)
};

__global__ void __launch_bounds__(NTHREADS, 1)
rnn_reg_kernel(const float* __restrict__ x,
               const float* __restrict__ W_ih0,
               const float* __restrict__ W_hh0,
               const float* __restrict__ b_ih0,
               const float* __restrict__ b_hh0,
               const float* __restrict__ W_ih1,
               const float* __restrict__ W_hh1,
               const float* __restrict__ b_ih1,
               const float* __restrict__ b_hh1,
               const float* __restrict__ fc_w,
               const float* __restrict__ fc_b,
               float* __restrict__ out)
{
    __shared__ GroupSmem gs[GROUPS];

    const int tid  = threadIdx.x;
    const int warp = tid >> 5;
    const int lane = tid & 31;
    const int g    = warp >> 1;      // group (batch element) within block
    const int half = warp & 1;       // which half of the 64 outputs
    const int j    = half * 32 + lane;
    const int e    = blockIdx.x * GROUPS + g;

    // Zero the h buffers (only buffer[1] strictly needs it; zero all).
    {
        float* z = (float*)gs;
        const int nz = (int)(sizeof(gs) / sizeof(float));
        for (int i = tid; i < nz; i += NTHREADS) z[i] = 0.f;
    }

    // ---- Load this lane's weight rows into registers (k-packed pairs) ----
    ull whh0r[32], wih1r[32], whh1r[32], wih0r[4];
    {
        const ulonglong2* p = (const ulonglong2*)(W_hh0 + j * HH);
        #pragma unroll
        for (int i = 0; i < 16; i++) { ulonglong2 v = p[i]; whh0r[2*i] = v.x; whh0r[2*i+1] = v.y; }
    }
    {
        const ulonglong2* p = (const ulonglong2*)(W_ih1 + j * HH);
        #pragma unroll
        for (int i = 0; i < 16; i++) { ulonglong2 v = p[i]; wih1r[2*i] = v.x; wih1r[2*i+1] = v.y; }
    }
    {
        const ulonglong2* p = (const ulonglong2*)(W_hh1 + j * HH);
        #pragma unroll
        for (int i = 0; i < 16; i++) { ulonglong2 v = p[i]; whh1r[2*i] = v.x; whh1r[2*i+1] = v.y; }
    }
    {
        const ulonglong2* p = (const ulonglong2*)(W_ih0 + j * 8);
        ulonglong2 v = p[0]; wih0r[0] = v.x; wih0r[1] = v.y;
        v = p[1];            wih0r[2] = v.x; wih0r[3] = v.y;
    }

    const float bv0 = b_ih0[j] + b_hh0[j];
    const float bv1 = b_ih1[j] + b_hh1[j];
    const float fw  = fc_w[j];
    const float fcb = fc_b[0];

    __syncthreads();

    const int barid = g + 1;  // named barriers 1..4 (0 reserved for syncthreads)

    // x row for this element: 8 floats per step = 2 ulonglong2 (4 packs).
    const ulonglong2* __restrict__ xr =
        (const ulonglong2*)(x + (size_t)e * TT * 8);

    ulonglong2 xa = xr[0];
    ulonglong2 xb = xr[1];

    float h0n = 0.f, h1n = 0.f;

    for (int t = 0; t < TT; t++) {
        const int wp = t & 1;
        const int rp = wp ^ 1;

        // Prefetch next step's x (independent of recurrence).
        const int tn = (t < TT - 1) ? (t + 1) : t;
        ulonglong2 nxa = xr[2 * tn];
        ulonglong2 nxb = xr[2 * tn + 1];

        // ---------- Layer 0: bias + x_t @ Wih0^T + h0_prev @ Whh0^T ----------
        ull acc[4];
        acc[0] = ffma2(xa.x, wih0r[0], 0ull);
        acc[1] = ffma2(xa.y, wih0r[1], 0ull);
        acc[2] = ffma2(xb.x, wih0r[2], 0ull);
        acc[3] = ffma2(xb.y, wih0r[3], 0ull);

        {
            const ulonglong2* hp = (const ulonglong2*)gs[g].h0[rp];  // broadcast LDS
            #pragma unroll
            for (int i = 0; i < 16; i++) {
                ulonglong2 hv = hp[i];
                acc[i & 3] = ffma2(hv.x, whh0r[2*i],     acc[i & 3]);
                acc[i & 3] = ffma2(hv.y, whh0r[2*i + 1], acc[i & 3]);
            }
        }
        {
            float2 f = unpk(fadd2(fadd2(acc[0], acc[1]), fadd2(acc[2], acc[3])));
            h0n = tanhf(bv0 + f.x + f.y);
        }
        gs[g].h0[wp][j] = h0n;

        asm volatile("bar.sync %0, 64;" :: "r"(barid) : "memory");

        // ---------- Layer 1: bias + h0_new @ Wih1^T + h1_prev @ Whh1^T ----------
        acc[0] = 0ull; acc[1] = 0ull; acc[2] = 0ull; acc[3] = 0ull;
        {
            const ulonglong2* hp = (const ulonglong2*)gs[g].h0[wp];
            #pragma unroll
            for (int i = 0; i < 16; i++) {
                ulonglong2 hv = hp[i];
                acc[i & 3] = ffma2(hv.x, wih1r[2*i],     acc[i & 3]);
                acc[i & 3] = ffma2(hv.y, wih1r[2*i + 1], acc[i & 3]);
            }
        }
        {
            const ulonglong2* hp = (const ulonglong2*)gs[g].h1[rp];
            #pragma unroll
            for (int i = 0; i < 16; i++) {
                ulonglong2 hv = hp[i];
                acc[i & 3] = ffma2(hv.x, whh1r[2*i],     acc[i & 3]);
                acc[i & 3] = ffma2(hv.y, whh1r[2*i + 1], acc[i & 3]);
            }
        }
        {
            float2 f = unpk(fadd2(fadd2(acc[0], acc[1]), fadd2(acc[2], acc[3])));
            h1n = tanhf(bv1 + f.x + f.y);
        }
        gs[g].h1[wp][j] = h1n;
        // No second barrier needed: next iteration's bar (after its layer-0 store)
        // orders this store before any cross-warp read of it, and the ping-pong
        // buffers remove the WAR hazards.

        xa = nxa;
        xb = nxb;
    }

    // ---------- FC: out[e] = sum_j h1[j] * fc_w[j] + fc_b ----------
    float s = h1n * fw;
    #pragma unroll
    for (int off = 16; off > 0; off >>= 1)
        s += __shfl_xor_sync(FULLMASK, s, off);
    if (lane == 0) gs[g].part[half] = s;
    asm volatile("bar.sync %0, 64;" :: "r"(barid) : "memory");
    if (half == 0 && lane == 0)
        out[e] = gs[g].part[0] + gs[g].part[1] + fcb;
}

extern "C" void kernel_launch(void* const* d_in, const int* in_sizes, int n_in,
                              void* d_out, int out_size)
{
    const float* x     = (const float*)d_in[0];
    const float* W_ih0 = (const float*)d_in[1];
    const float* W_hh0 = (const float*)d_in[2];
    const float* b_ih0 = (const float*)d_in[3];
    const float* b_hh0 = (const float*)d_in[4];
    const float* W_ih1 = (const float*)d_in[5];
    const float* W_hh1 = (const float*)d_in[6];
    const float* b_ih1 = (const float*)d_in[7];
    const float* b_hh1 = (const float*)d_in[8];
    const float* fc_w  = (const float*)d_in[9];
    const float* fc_b  = (const float*)d_in[10];
    float* out = (float*)d_out;

    dim3 grid(BB / GROUPS);   // 512 blocks
    dim3 block(NTHREADS);     // 8 warps = 4 elements x 2 warps
    rnn_reg_kernel<<<grid, block>>>(
        x, W_ih0, W_hh0, b_ih0, b_hh0,
        W_ih1, W_hh1, b_ih1, b_hh1,
        fc_w, fc_b, out);
}

// round 4
// speedup vs baseline: 1.6584x; 1.2124x over previous
#include <cuda_runtime.h>

// RNNModel: 2-layer tanh RNN + FC, B=2048, T=512, I=8, H=64.
// R3: k-split register-resident weights to kill R2's register spills.
//  - 1 block = 128 threads = 4 warps = 1 batch element.
//  - warp w: jh = w&1 (output half, j = jh*32+lane), kh = w>>1 (k half).
//  - Each lane holds HALF a row of W_hh0/W_ih1/W_hh1 (16 ull = 32 regs each,
//    96 regs total) -> ~135 regs peak, 3 blocks/SM, no spills.
//  - kh=1 warps produce partial sums via SMEM; kh=0 warps finalize (+bias,+x-term,
//    tanh) -- 3 __syncthreads per step (Whh1*h1_prev partial overlapped with the
//    h0 finalize to avoid a 4th).
//  - h0/h1 double-buffered in SMEM; all SMEM reads broadcast or conflict-free.

#define TT 512
#define HH 64
#define NTHREADS 128
#define BB 2048
#define FULLMASK 0xffffffffu

typedef unsigned long long ull;

__device__ __forceinline__ ull ffma2(ull a, ull b, ull c) {
    ull d;
    asm("fma.rn.f32x2 %0, %1, %2, %3;" : "=l"(d) : "l"(a), "l"(b), "l"(c));
    return d;
}
__device__ __forceinline__ ull fadd2(ull a, ull b) {
    ull d;
    asm("add.rn.f32x2 %0, %1, %2;" : "=l"(d) : "l"(a), "l"(b));
    return d;
}
__device__ __forceinline__ float red2(ull a0, ull a1, ull a2, ull a3) {
    ull s = fadd2(fadd2(a0, a1), fadd2(a2, a3));
    float2 f;
    asm("mov.b64 {%0, %1}, %2;" : "=f"(f.x), "=f"(f.y) : "l"(s));
    return f.x + f.y;
}

__global__ void __launch_bounds__(NTHREADS)
rnn_ksplit_kernel(const float* __restrict__ x,
                  const float* __restrict__ W_ih0,
                  const float* __restrict__ W_hh0,
                  const float* __restrict__ b_ih0,
                  const float* __restrict__ b_hh0,
                  const float* __restrict__ W_ih1,
                  const float* __restrict__ W_hh1,
                  const float* __restrict__ b_ih1,
                  const float* __restrict__ b_hh1,
                  const float* __restrict__ fc_w,
                  const float* __restrict__ fc_b,
                  float* __restrict__ out)
{
    __shared__ float sh0[2][HH];    // layer-0 hidden, double-buffered
    __shared__ float sh1[2][HH];    // layer-1 hidden, double-buffered
    __shared__ float sp0[HH];       // layer-0 k-partials (from kh=1)
    __shared__ float sp1[HH];       // layer-1 k-partials (from kh=1)
    __shared__ float sfc[2];        // FC partials

    const int tid  = threadIdx.x;
    const int warp = tid >> 5;
    const int lane = tid & 31;
    const int jh   = warp & 1;
    const int kh   = warp >> 1;          // 0: finalizer half, 1: partial half
    const int j    = jh * 32 + lane;
    const int e    = blockIdx.x;

    // Zero the read-side buffers for t=0 (h buffers; partials are written before read).
    if (tid < HH) { sh0[1][tid] = 0.f; sh1[1][tid] = 0.f; }

    // ---- Per-lane weight halves in registers (k in [kh*32, kh*32+32)) ----
    ull whh0h[16], wih1h[16], whh1h[16];
    {
        const ulonglong2* p = (const ulonglong2*)(W_hh0 + j * HH + kh * 32);
        #pragma unroll
        for (int i = 0; i < 8; i++) { ulonglong2 v = p[i]; whh0h[2*i] = v.x; whh0h[2*i+1] = v.y; }
    }
    {
        const ulonglong2* p = (const ulonglong2*)(W_ih1 + j * HH + kh * 32);
        #pragma unroll
        for (int i = 0; i < 8; i++) { ulonglong2 v = p[i]; wih1h[2*i] = v.x; wih1h[2*i+1] = v.y; }
    }
    {
        const ulonglong2* p = (const ulonglong2*)(W_hh1 + j * HH + kh * 32);
        #pragma unroll
        for (int i = 0; i < 8; i++) { ulonglong2 v = p[i]; whh1h[2*i] = v.x; whh1h[2*i+1] = v.y; }
    }

    // Only the finalizer (kh=0) needs W_ih0 (I=8 < 32) and the biases.
    ull wih0r[4];
    float bv0 = 0.f, bv1 = 0.f;
    if (kh == 0) {
        const ulonglong2* p = (const ulonglong2*)(W_ih0 + j * 8);
        ulonglong2 v = p[0]; wih0r[0] = v.x; wih0r[1] = v.y;
        v = p[1];            wih0r[2] = v.x; wih0r[3] = v.y;
        bv0 = b_ih0[j] + b_hh0[j];
        bv1 = b_ih1[j] + b_hh1[j];
    }

    __syncthreads();

    const ulonglong2* __restrict__ xr = (const ulonglong2*)(x + (size_t)e * TT * 8);

    float h1n = 0.f;

    for (int t = 0; t < TT; t++) {
        const int wp = t & 1;
        const int rp = wp ^ 1;

        // ---------- Layer 0 partial: (my k-half of) Whh0 . h0_prev ----------
        ull a0 = 0, a1 = 0, a2 = 0, a3 = 0;
        if (kh == 0) {                 // + x_t @ Wih0^T (k = 0..7 lives in half 0)
            ulonglong2 xa = xr[2 * t];
            ulonglong2 xb = xr[2 * t + 1];
            a0 = ffma2(xa.x, wih0r[0], a0);
            a1 = ffma2(xa.y, wih0r[1], a1);
            a2 = ffma2(xb.x, wih0r[2], a2);
            a3 = ffma2(xb.y, wih0r[3], a3);
        }
        {
            const ulonglong2* hp = (const ulonglong2*)(sh0[rp] + kh * 32); // broadcast
            #pragma unroll
            for (int i = 0; i < 8; i++) {
                ulonglong2 hv = hp[i];
                ull w0 = whh0h[2*i], w1 = whh0h[2*i+1];
                if ((i & 1) == 0) { a0 = ffma2(hv.x, w0, a0); a1 = ffma2(hv.y, w1, a1); }
                else              { a2 = ffma2(hv.x, w0, a2); a3 = ffma2(hv.y, w1, a3); }
            }
        }
        float part0 = red2(a0, a1, a2, a3);
        if (kh == 1) sp0[j] = part0;

        __syncthreads();   // bar A: p0 visible to finalizer

        // Finalizer: h0_new = tanh(bias + own + partner partial); store.
        if (kh == 0) {
            float h0n = tanhf(bv0 + part0 + sp0[j]);
            sh0[wp][j] = h0n;
        }

        // ---------- Layer 1 partial #1: Whh1 . h1_prev (overlaps h0 finalize) ----------
        ull c0 = 0, c1 = 0, c2 = 0, c3 = 0;
        {
            const ulonglong2* hp = (const ulonglong2*)(sh1[rp] + kh * 32);
            #pragma unroll
            for (int i = 0; i < 8; i++) {
                ulonglong2 hv = hp[i];
                ull w0 = whh1h[2*i], w1 = whh1h[2*i+1];
                if ((i & 1) == 0) { c0 = ffma2(hv.x, w0, c0); c1 = ffma2(hv.y, w1, c1); }
                else              { c2 = ffma2(hv.x, w0, c2); c3 = ffma2(hv.y, w1, c3); }
            }
        }

        __syncthreads();   // bar B: h0_new visible to everyone

        // ---------- Layer 1 partial #2: Wih1 . h0_new ----------
        {
            const ulonglong2* hp = (const ulonglong2*)(sh0[wp] + kh * 32);
            #pragma unroll
            for (int i = 0; i < 8; i++) {
                ulonglong2 hv = hp[i];
                ull w0 = wih1h[2*i], w1 = wih1h[2*i+1];
                if ((i & 1) == 0) { c0 = ffma2(hv.x, w0, c0); c1 = ffma2(hv.y, w1, c1); }
                else              { c2 = ffma2(hv.x, w0, c2); c3 = ffma2(hv.y, w1, c3); }
            }
        }
        float part1 = red2(c0, c1, c2, c3);
        if (kh == 1) sp1[j] = part1;

        __syncthreads();   // bar C: p1 visible to finalizer

        if (kh == 0) {
            h1n = tanhf(bv1 + part1 + sp1[j]);
            sh1[wp][j] = h1n;
        }
        // No bar D: the next consumer of sh1[wp] is the Whh1 partial after the
        // NEXT iteration's bar A; double-buffering removes the WAR hazard.
    }

    // ---------- FC: out[e] = sum_j h1_last[j] * fc_w[j] + fc_b ----------
    if (kh == 0) {
        float s = h1n * fc_w[j];
        #pragma unroll
        for (int off = 16; off > 0; off >>= 1)
            s += __shfl_xor_sync(FULLMASK, s, off);
        if (lane == 0) sfc[jh] = s;
    }
    __syncthreads();
    if (tid == 0)
        out[e] = sfc[0] + sfc[1] + fc_b[0];
}

extern "C" void kernel_launch(void* const* d_in, const int* in_sizes, int n_in,
                              void* d_out, int out_size)
{
    const float* x     = (const float*)d_in[0];
    const float* W_ih0 = (const float*)d_in[1];
    const float* W_hh0 = (const float*)d_in[2];
    const float* b_ih0 = (const float*)d_in[3];
    const float* b_hh0 = (const float*)d_in[4];
    const float* W_ih1 = (const float*)d_in[5];
    const float* W_hh1 = (const float*)d_in[6];
    const float* b_ih1 = (const float*)d_in[7];
    const float* b_hh1 = (const float*)d_in[8];
    const float* fc_w  = (const float*)d_in[9];
    const float* fc_b  = (const float*)d_in[10];
    float* out = (float*)d_out;

    dim3 grid(BB);          // 2048 blocks, one batch element each
    dim3 block(NTHREADS);   // 128 threads = 4 warps
    rnn_ksplit_kernel<<<grid, block>>>(
        x, W_ih0, W_hh0, b_ih0, b_hh0,
        W_ih1, W_hh1, b_ih1, b_hh1,
        fc_w, fc_b, out);
}

// round 5
// speedup vs baseline: 2.3816x; 1.4361x over previous
#include <cuda_runtime.h>

// RNNModel: 2-layer tanh RNN + FC, B=2048, T=512, I=8, H=64.
// R4: one-barrier-per-step pipelined design.
//  - 1 block = 128 threads = 4 warps = 1 batch element.
//  - lane = (ks, jl): ks = lane>>4 (k half), jl = lane&15; j = warp*16 + jl.
//  - Each lane holds HALF-k rows (j fixed) of W_hh0/W_ih1/W_hh1 in registers.
//  - k-reduction via shfl.xor(16) (no SMEM partials, no extra barriers).
//  - Layer 1 lags one step: at iter i compute h0[i] AND h1[i-1] -> both read
//    only pre-barrier state -> ONE __syncthreads per step; chains dual-issue.
//  - h0 loads shared between Whh0 and Wih1 matvecs (16 LDS.128/warp/step).
//  - h buffers skewed (+4 floats between halves) -> dual-broadcast LDS conflict-free.
//  - tanh via clamped ex2.approx/rcp.approx identity (~1e-7 abs err, 6 ops).

#define TT 512
#define HH 64
#define NTHREADS 128
#define BB 2048
#define FULLMASK 0xffffffffu
#define HROW 72          // 64 + skew pad; half0 at [0,32), half1 at [36,68)

typedef unsigned long long ull;

__device__ __forceinline__ ull ffma2(ull a, ull b, ull c) {
    ull d; asm("fma.rn.f32x2 %0, %1, %2, %3;" : "=l"(d) : "l"(a), "l"(b), "l"(c)); return d;
}
__device__ __forceinline__ ull fadd2(ull a, ull b) {
    ull d; asm("add.rn.f32x2 %0, %1, %2;" : "=l"(d) : "l"(a), "l"(b)); return d;
}
__device__ __forceinline__ float hsum4(ull a0, ull a1, ull a2, ull a3) {
    ull s = fadd2(fadd2(a0, a1), fadd2(a2, a3));
    float2 f; asm("mov.b64 {%0, %1}, %2;" : "=f"(f.x), "=f"(f.y) : "l"(s));
    return f.x + f.y;
}
__device__ __forceinline__ float fast_tanh(float x) {
    // tanh(x) = 1 - 2/(exp(2x)+1); clamp so ex2 can't overflow.
    float xc = fminf(fmaxf(x, -15.f), 15.f);
    float e; asm("ex2.approx.f32 %0, %1;" : "=f"(e) : "f"(xc * 2.8853900817779268f)); // 2*log2(e)
    float r; asm("rcp.approx.f32 %0, %1;" : "=f"(r) : "f"(e + 1.f));
    return fmaf(-2.f, r, 1.f);
}

__global__ void __launch_bounds__(NTHREADS, 3)
rnn_pipe_kernel(const float* __restrict__ x,
                const float* __restrict__ W_ih0,
                const float* __restrict__ W_hh0,
                const float* __restrict__ b_ih0,
                const float* __restrict__ b_hh0,
                const float* __restrict__ W_ih1,
                const float* __restrict__ W_hh1,
                const float* __restrict__ b_ih1,
                const float* __restrict__ b_hh1,
                const float* __restrict__ fc_w,
                const float* __restrict__ fc_b,
                float* __restrict__ out)
{
    __shared__ float sh0[2][HROW];
    __shared__ float sh1[2][HROW];
    __shared__ float sfc[4];

    const int tid  = threadIdx.x;
    const int warp = tid >> 5;
    const int lane = tid & 31;
    const int jl   = lane & 15;
    const int ks   = lane >> 4;          // k half: 0 -> k[0,32), 1 -> k[32,64)
    const int j    = warp * 16 + jl;
    const int jidx = j + ((j >> 5) << 2);    // skewed store index
    const int khoff = ks * 36;               // skewed read offset (floats)
    const int e    = blockIdx.x;

    // Zero the t=0 read buffers (h0[-1], and h1[-1] read at i=1).
    if (tid < HROW) { sh0[1][tid] = 0.f; sh1[1][tid] = 0.f; }

    // ---- Per-lane half-k weight rows in registers ----
    ull whh0h[16], wih1h[16], whh1h[16], wih0r[4];
    {
        const ulonglong2* p = (const ulonglong2*)(W_hh0 + j * HH + ks * 32);
        #pragma unroll
        for (int i = 0; i < 8; i++) { ulonglong2 v = p[i]; whh0h[2*i] = v.x; whh0h[2*i+1] = v.y; }
    }
    {
        const ulonglong2* p = (const ulonglong2*)(W_ih1 + j * HH + ks * 32);
        #pragma unroll
        for (int i = 0; i < 8; i++) { ulonglong2 v = p[i]; wih1h[2*i] = v.x; wih1h[2*i+1] = v.y; }
    }
    {
        const ulonglong2* p = (const ulonglong2*)(W_hh1 + j * HH + ks * 32);
        #pragma unroll
        for (int i = 0; i < 8; i++) { ulonglong2 v = p[i]; whh1h[2*i] = v.x; whh1h[2*i+1] = v.y; }
    }
    {
        const ulonglong2* p = (const ulonglong2*)(W_ih0 + j * 8);  // k 0..7 (in half 0)
        ulonglong2 v = p[0]; wih0r[0] = v.x; wih0r[1] = v.y;
        v = p[1];            wih0r[2] = v.x; wih0r[3] = v.y;
    }

    const float bv0 = b_ih0[j] + b_hh0[j];
    const float bv1 = b_ih1[j] + b_hh1[j];
    float fcw = fc_w[j];
    if (ks == 1) fcw = 0.f;              // avoid double-count in FC reduce

    __syncthreads();

    const ulonglong2* __restrict__ xr = (const ulonglong2*)(x + (size_t)e * TT * 8);
    ulonglong2 xa = xr[0], xb = xr[1];

    // ---- Peel i=0: h0[0] = tanh(bv0 + x0.Wih0)  (h0[-1]=0, no L1 yet) ----
    {
        ull a0 = 0, a1 = 0, a2 = 0, a3 = 0;
        if (ks == 0) {
            a0 = ffma2(xa.x, wih0r[0], a0); a1 = ffma2(xa.y, wih0r[1], a1);
            a2 = ffma2(xb.x, wih0r[2], a2); a3 = ffma2(xb.y, wih0r[3], a3);
        }
        float s0 = hsum4(a0, a1, a2, a3);
        s0 += __shfl_xor_sync(FULLMASK, s0, 16);
        float h0n = fast_tanh(bv0 + s0);
        if (ks == 0) sh0[0][jidx] = h0n;
        __syncthreads();
        xa = xr[2]; xb = xr[3];
    }

    // ---- Main loop i = 1 .. TT-1: compute h0[i] and h1[i-1]; one barrier ----
    for (int i = 1; i < TT; i++) {
        const int w = i & 1;
        float*       h0w = sh0[w];
        const float* h0r = sh0[w ^ 1];   // h0[i-1]
        float*       h1w = sh1[w ^ 1];   // h1[i-1] dest
        const float* h1r = sh1[w];       // h1[i-2]

        const int tn = (i + 1 < TT) ? (i + 1) : (TT - 1);
        ulonglong2 nxa = xr[2 * tn], nxb = xr[2 * tn + 1];

        ull a0 = 0, a1 = 0, a2 = 0, a3 = 0;   // layer 0
        ull c0 = 0, c1 = 0, c2 = 0, c3 = 0;   // layer 1
        if (ks == 0) {
            a0 = ffma2(xa.x, wih0r[0], a0); a1 = ffma2(xa.y, wih0r[1], a1);
            a2 = ffma2(xb.x, wih0r[2], a2); a3 = ffma2(xb.y, wih0r[3], a3);
        }

        const ulonglong2* hp0 = (const ulonglong2*)(h0r + khoff);
        const ulonglong2* hp1 = (const ulonglong2*)(h1r + khoff);
        #pragma unroll
        for (int q = 0; q < 8; q++) {        // shared h0 loads: Whh0 + Wih1
            ulonglong2 hv = hp0[q];
            if ((q & 1) == 0) {
                a0 = ffma2(hv.x, whh0h[2*q], a0); a1 = ffma2(hv.y, whh0h[2*q+1], a1);
                c0 = ffma2(hv.x, wih1h[2*q], c0); c1 = ffma2(hv.y, wih1h[2*q+1], c1);
            } else {
                a2 = ffma2(hv.x, whh0h[2*q], a2); a3 = ffma2(hv.y, whh0h[2*q+1], a3);
                c2 = ffma2(hv.x, wih1h[2*q], c2); c3 = ffma2(hv.y, wih1h[2*q+1], c3);
            }
        }
        #pragma unroll
        for (int q = 0; q < 8; q++) {        // Whh1 . h1[i-2]
            ulonglong2 hv = hp1[q];
            if ((q & 1) == 0) {
                c0 = ffma2(hv.x, whh1h[2*q], c0); c1 = ffma2(hv.y, whh1h[2*q+1], c1);
            } else {
                c2 = ffma2(hv.x, whh1h[2*q], c2); c3 = ffma2(hv.y, whh1h[2*q+1], c3);
            }
        }

        float s0 = hsum4(a0, a1, a2, a3);
        s0 += __shfl_xor_sync(FULLMASK, s0, 16);
        float h0n = fast_tanh(bv0 + s0);

        float s1 = hsum4(c0, c1, c2, c3);
        s1 += __shfl_xor_sync(FULLMASK, s1, 16);
        float h1n = fast_tanh(bv1 + s1);

        if (ks == 0) { h0w[jidx] = h0n; h1w[jidx] = h1n; }
        __syncthreads();
        xa = nxa; xb = nxb;
    }

    // ---- Tail i = TT: h1[TT-1] from h0[TT-1] and h1[TT-2] ----
    float h1last;
    {
        const float* h0r = sh0[(TT - 1) & 1];  // h0[TT-1]
        const float* h1r = sh1[TT & 1];        // h1[TT-2]
        ull c0 = 0, c1 = 0, c2 = 0, c3 = 0;
        const ulonglong2* hp0 = (const ulonglong2*)(h0r + khoff);
        const ulonglong2* hp1 = (const ulonglong2*)(h1r + khoff);
        #pragma unroll
        for (int q = 0; q < 8; q++) {
            ulonglong2 hv = hp0[q];
            if ((q & 1) == 0) {
                c0 = ffma2(hv.x, wih1h[2*q], c0); c1 = ffma2(hv.y, wih1h[2*q+1], c1);
            } else {
                c2 = ffma2(hv.x, wih1h[2*q], c2); c3 = ffma2(hv.y, wih1h[2*q+1], c3);
            }
        }
        #pragma unroll
        for (int q = 0; q < 8; q++) {
            ulonglong2 hv = hp1[q];
            if ((q & 1) == 0) {
                c0 = ffma2(hv.x, whh1h[2*q], c0); c1 = ffma2(hv.y, whh1h[2*q+1], c1);
            } else {
                c2 = ffma2(hv.x, whh1h[2*q], c2); c3 = ffma2(hv.y, whh1h[2*q+1], c3);
            }
        }
        float s1 = hsum4(c0, c1, c2, c3);
        s1 += __shfl_xor_sync(FULLMASK, s1, 16);
        h1last = fast_tanh(bv1 + s1);
    }

    // ---- FC: out[e] = sum_j h1_last[j] * fc_w[j] + fc_b ----
    float v = h1last * fcw;                  // fcw==0 on ks=1 lanes
    #pragma unroll
    for (int off = 16; off > 0; off >>= 1)
        v += __shfl_xor_sync(FULLMASK, v, off);
    if (lane == 0) sfc[warp] = v;
    __syncthreads();
    if (tid == 0)
        out[e] = sfc[0] + sfc[1] + sfc[2] + sfc[3] + fc_b[0];
}

extern "C" void kernel_launch(void* const* d_in, const int* in_sizes, int n_in,
                              void* d_out, int out_size)
{
    const float* x     = (const float*)d_in[0];
    const float* W_ih0 = (const float*)d_in[1];
    const float* W_hh0 = (const float*)d_in[2];
    const float* b_ih0 = (const float*)d_in[3];
    const float* b_hh0 = (const float*)d_in[4];
    const float* W_ih1 = (const float*)d_in[5];
    const float* W_hh1 = (const float*)d_in[6];
    const float* b_ih1 = (const float*)d_in[7];
    const float* b_hh1 = (const float*)d_in[8];
    const float* fc_w  = (const float*)d_in[9];
    const float* fc_b  = (const float*)d_in[10];
    float* out = (float*)d_out;

    dim3 grid(BB);          // 2048 blocks, one batch element each
    dim3 block(NTHREADS);   // 128 threads = 4 warps
    rnn_pipe_kernel<<<grid, block>>>(
        x, W_ih0, W_hh0, b_ih0, b_hh0,
        W_ih1, W_hh1, b_ih1, b_hh1,
        fc_w, fc_b, out);
}

// round 6
// speedup vs baseline: 2.6938x; 1.1311x over previous
#include <cuda_runtime.h>

// RNNModel: 2-layer tanh RNN + FC, B=2048, T=512, I=8, H=64.
// R5: R4 design + instruction diet.
//  - 1 block = 128 threads = 4 warps = 1 batch element.
//  - lane = (ks, jl): ks = lane>>4 (k half), jl = lane&15; j = warp*16 + jl.
//  - Half-k weight rows in registers; k-reduce via shfl.xor(16).
//  - Layer 1 lags one step -> ONE __syncthreads per step.
//  - t-loop unrolled x2 with compile-time buffer parity (no flip ALU);
//    all SMEM pointers hoisted; x walked by pointer increment.
//  - tanh = 1 - 2/(exp2(2x*log2e)+1), unclamped (inf/0 limits give +-1 exactly).

#define TT 512
#define HH 64
#define NTHREADS 128
#define BB 2048
#define FULLMASK 0xffffffffu
#define HROW 72          // 64 + skew pad; half0 at [0,32), half1 at [36,68)

typedef unsigned long long ull;

__device__ __forceinline__ ull ffma2(ull a, ull b, ull c) {
    ull d; asm("fma.rn.f32x2 %0, %1, %2, %3;" : "=l"(d) : "l"(a), "l"(b), "l"(c)); return d;
}
__device__ __forceinline__ ull fadd2(ull a, ull b) {
    ull d; asm("add.rn.f32x2 %0, %1, %2;" : "=l"(d) : "l"(a), "l"(b)); return d;
}
__device__ __forceinline__ float hsum4(ull a0, ull a1, ull a2, ull a3) {
    ull s = fadd2(fadd2(a0, a1), fadd2(a2, a3));
    float2 f; asm("mov.b64 {%0, %1}, %2;" : "=f"(f.x), "=f"(f.y) : "l"(s));
    return f.x + f.y;
}
__device__ __forceinline__ float fast_tanh(float x) {
    // tanh(x) = 1 - 2/(exp(2x)+1). No clamp: ex2->inf gives 1-2*rcp(inf)=1,
    // ex2->0 gives 1-2*rcp(1)=-1 -- correct saturation for free.
    float e; asm("ex2.approx.f32 %0, %1;" : "=f"(e) : "f"(x * 2.8853900817779268f));
    float r; asm("rcp.approx.f32 %0, %1;" : "=f"(r) : "f"(e + 1.f));
    return fmaf(-2.f, r, 1.f);
}

__global__ void __launch_bounds__(NTHREADS, 3)
rnn_pipe2_kernel(const float* __restrict__ x,
                 const float* __restrict__ W_ih0,
                 const float* __restrict__ W_hh0,
                 const float* __restrict__ b_ih0,
                 const float* __restrict__ b_hh0,
                 const float* __restrict__ W_ih1,
                 const float* __restrict__ W_hh1,
                 const float* __restrict__ b_ih1,
                 const float* __restrict__ b_hh1,
                 const float* __restrict__ fc_w,
                 const float* __restrict__ fc_b,
                 float* __restrict__ out)
{
    __shared__ float s00[HROW];   // sh0 buf 0
    __shared__ float s01[HROW];   // sh0 buf 1
    __shared__ float s10[HROW];   // sh1 buf 0
    __shared__ float s11[HROW];   // sh1 buf 1
    __shared__ float sfc[4];

    const int tid  = threadIdx.x;
    const int warp = tid >> 5;
    const int lane = tid & 31;
    const int jl   = lane & 15;
    const int ks   = lane >> 4;              // k half
    const int j    = warp * 16 + jl;
    const int jidx = j + ((j >> 5) << 2);    // skewed store index
    const int khoff = ks * 36;               // skewed read offset (floats)
    const int e    = blockIdx.x;

    // Zero the t=0 read-side h1 buffer (h1[-1]); others written before read.
    if (tid < HROW) { s11[tid] = 0.f; s10[tid] = 0.f; }

    // ---- Per-lane half-k weight rows in registers ----
    ull whh0h[16], wih1h[16], whh1h[16], wih0r[4];
    {
        const ulonglong2* p = (const ulonglong2*)(W_hh0 + j * HH + ks * 32);
        #pragma unroll
        for (int i = 0; i < 8; i++) { ulonglong2 v = p[i]; whh0h[2*i] = v.x; whh0h[2*i+1] = v.y; }
    }
    {
        const ulonglong2* p = (const ulonglong2*)(W_ih1 + j * HH + ks * 32);
        #pragma unroll
        for (int i = 0; i < 8; i++) { ulonglong2 v = p[i]; wih1h[2*i] = v.x; wih1h[2*i+1] = v.y; }
    }
    {
        const ulonglong2* p = (const ulonglong2*)(W_hh1 + j * HH + ks * 32);
        #pragma unroll
        for (int i = 0; i < 8; i++) { ulonglong2 v = p[i]; whh1h[2*i] = v.x; whh1h[2*i+1] = v.y; }
    }
    {
        const ulonglong2* p = (const ulonglong2*)(W_ih0 + j * 8);  // k 0..7 (half 0)
        ulonglong2 v = p[0]; wih0r[0] = v.x; wih0r[1] = v.y;
        v = p[1];            wih0r[2] = v.x; wih0r[3] = v.y;
    }

    const float bv0 = b_ih0[j] + b_hh0[j];
    const float bv1 = b_ih1[j] + b_hh1[j];
    float fcw = fc_w[j];
    if (ks == 1) fcw = 0.f;                  // avoid double-count in FC reduce

    // Hoisted skew-baked read pointers (loop-invariant).
    const ulonglong2* pA = (const ulonglong2*)(s00 + khoff);  // h0 buf0
    const ulonglong2* pB = (const ulonglong2*)(s01 + khoff);  // h0 buf1
    const ulonglong2* pC = (const ulonglong2*)(s10 + khoff);  // h1 buf0
    const ulonglong2* pD = (const ulonglong2*)(s11 + khoff);  // h1 buf1

    __syncthreads();

    const ulonglong2* __restrict__ xr = (const ulonglong2*)(x + (size_t)e * TT * 8);
    ulonglong2 xa = xr[0], xb = xr[1];

    // ---- Peel i=0: h0[0] = tanh(bv0 + x0.Wih0); store to s00 ----
    {
        ull a0 = 0, a1 = 0, a2 = 0, a3 = 0;
        if (ks == 0) {
            a0 = ffma2(xa.x, wih0r[0], a0); a1 = ffma2(xa.y, wih0r[1], a1);
            a2 = ffma2(xb.x, wih0r[2], a2); a3 = ffma2(xb.y, wih0r[3], a3);
        }
        float s0 = hsum4(a0, a1, a2, a3);
        s0 += __shfl_xor_sync(FULLMASK, s0, 16);
        float h0n = fast_tanh(bv0 + s0);
        if (ks == 0) s00[jidx] = h0n;
        __syncthreads();
        xa = xr[2]; xb = xr[3];
    }

    const ulonglong2* xp = xr + 4;           // x[t=2], walked by increment
    float h1n = 0.f;

    // Body: computes h0[i] (from H0R = h0[i-1]) and h1[i-1] (from H0R and H1R
    // = h1[i-2]); stores to H0W/H1W; one barrier. PF: prefetch next x.
#define STEP_BODY(H0R, H1R, H0W, H1W, PF)                                        \
    {                                                                            \
        ull a0 = 0, a1 = 0, a2 = 0, a3 = 0;                                      \
        ull c0 = 0, c1 = 0, c2 = 0, c3 = 0;                                      \
        if (ks == 0) {                                                           \
            a0 = ffma2(xa.x, wih0r[0], a0); a1 = ffma2(xa.y, wih0r[1], a1);      \
            a2 = ffma2(xb.x, wih0r[2], a2); a3 = ffma2(xb.y, wih0r[3], a3);      \
        }                                                                        \
        ulonglong2 nxa, nxb;                                                     \
        if (PF) { nxa = xp[0]; nxb = xp[1]; xp += 2; }                           \
        _Pragma("unroll")                                                        \
        for (int q = 0; q < 8; q++) {                                            \
            ulonglong2 hv = H0R[q];                                              \
            if ((q & 1) == 0) {                                                  \
                a0 = ffma2(hv.x, whh0h[2*q], a0); a1 = ffma2(hv.y, whh0h[2*q+1], a1); \
                c0 = ffma2(hv.x, wih1h[2*q], c0); c1 = ffma2(hv.y, wih1h[2*q+1], c1); \
            } else {                                                             \
                a2 = ffma2(hv.x, whh0h[2*q], a2); a3 = ffma2(hv.y, whh0h[2*q+1], a3); \
                c2 = ffma2(hv.x, wih1h[2*q], c2); c3 = ffma2(hv.y, wih1h[2*q+1], c3); \
            }                                                                    \
        }                                                                        \
        _Pragma("unroll")                                                        \
        for (int q = 0; q < 8; q++) {                                            \
            ulonglong2 hv = H1R[q];                                              \
            if ((q & 1) == 0) {                                                  \
                c0 = ffma2(hv.x, whh1h[2*q], c0); c1 = ffma2(hv.y, whh1h[2*q+1], c1); \
            } else {                                                             \
                c2 = ffma2(hv.x, whh1h[2*q], c2); c3 = ffma2(hv.y, whh1h[2*q+1], c3); \
            }                                                                    \
        }                                                                        \
        float s0 = hsum4(a0, a1, a2, a3);                                        \
        s0 += __shfl_xor_sync(FULLMASK, s0, 16);                                 \
        float h0n = fast_tanh(bv0 + s0);                                         \
        float s1 = hsum4(c0, c1, c2, c3);                                        \
        s1 += __shfl_xor_sync(FULLMASK, s1, 16);                                 \
        h1n = fast_tanh(bv1 + s1);                                               \
        if (ks == 0) { H0W[jidx] = h0n; H1W[jidx] = h1n; }                       \
        __syncthreads();                                                         \
        if (PF) { xa = nxa; xb = nxb; }                                          \
    }

    // i = 1..510 as 255 unrolled pairs (odd then even parity).
    for (int iu = 0; iu < 255; iu++) {
        STEP_BODY(pA, pD, s01, s10, 1);   // i odd:  h0r=s00, h1r=s11 -> s01, s10
        STEP_BODY(pB, pC, s00, s11, 1);   // i even: h0r=s01, h1r=s10 -> s00, s11
    }
    // i = 511 (odd), no prefetch needed.
    STEP_BODY(pA, pD, s01, s10, 0);

    // ---- Tail: h1[511] from h0[511] (s01) and h1[510] (s10) ----
    {
        ull c0 = 0, c1 = 0, c2 = 0, c3 = 0;
        #pragma unroll
        for (int q = 0; q < 8; q++) {
            ulonglong2 hv = pB[q];
            if ((q & 1) == 0) { c0 = ffma2(hv.x, wih1h[2*q], c0); c1 = ffma2(hv.y, wih1h[2*q+1], c1); }
            else              { c2 = ffma2(hv.x, wih1h[2*q], c2); c3 = ffma2(hv.y, wih1h[2*q+1], c3); }
        }
        #pragma unroll
        for (int q = 0; q < 8; q++) {
            ulonglong2 hv = pC[q];
            if ((q & 1) == 0) { c0 = ffma2(hv.x, whh1h[2*q], c0); c1 = ffma2(hv.y, whh1h[2*q+1], c1); }
            else              { c2 = ffma2(hv.x, whh1h[2*q], c2); c3 = ffma2(hv.y, whh1h[2*q+1], c3); }
        }
        float s1 = hsum4(c0, c1, c2, c3);
        s1 += __shfl_xor_sync(FULLMASK, s1, 16);
        h1n = fast_tanh(bv1 + s1);
    }

    // ---- FC: out[e] = sum_j h1_last[j] * fc_w[j] + fc_b ----
    float v = h1n * fcw;                     // fcw==0 on ks=1 lanes
    #pragma unroll
    for (int off = 16; off > 0; off >>= 1)
        v += __shfl_xor_sync(FULLMASK, v, off);
    if (lane == 0) sfc[warp] = v;
    __syncthreads();
    if (tid == 0)
        out[e] = sfc[0] + sfc[1] + sfc[2] + sfc[3] + fc_b[0];
#undef STEP_BODY
}

extern "C" void kernel_launch(void* const* d_in, const int* in_sizes, int n_in,
                              void* d_out, int out_size)
{
    const float* x     = (const float*)d_in[0];
    const float* W_ih0 = (const float*)d_in[1];
    const float* W_hh0 = (const float*)d_in[2];
    const float* b_ih0 = (const float*)d_in[3];
    const float* b_hh0 = (const float*)d_in[4];
    const float* W_ih1 = (const float*)d_in[5];
    const float* W_hh1 = (const float*)d_in[6];
    const float* b_ih1 = (const float*)d_in[7];
    const float* b_hh1 = (const float*)d_in[8];
    const float* fc_w  = (const float*)d_in[9];
    const float* fc_b  = (const float*)d_in[10];
    float* out = (float*)d_out;

    dim3 grid(BB);          // 2048 blocks, one batch element each
    dim3 block(NTHREADS);   // 128 threads = 4 warps
    rnn_pipe2_kernel<<<grid, block>>>(
        x, W_ih0, W_hh0, b_ih0, b_hh0,
        W_ih1, W_hh1, b_ih1, b_hh1,
        fc_w, fc_b, out);
}